// round 13
// baseline (speedup 1.0000x reference)
#include <cuda_runtime.h>
#include <cstdint>

#define B_ROWS 131072
#define DIM 64
#define D_IN 32
#define TAILB 3.0f
#define TM 16
#define THREADS 256

#define XT_S 33
#define ST_S 776

#define SM_XT    0        // 16*33*4 = 2112
#define SM_BIAS  2112     // 1792*4
#define SM_SB    9280     // 1792*4
#define SM_RM    16448    // 48*4
#define SM_AF1   16640    // 8192
#define SM_AF2   24832    // 8192
#define SM_STASH 33024    // 16*776*4 = 49664
#define SM_TOTAL 82688

typedef unsigned int u32;

__device__ float g_sbg[1792];            // col maxes: [0,512) W1, [512,1024) W2, [1024,1792) W3(pad)
__device__ uint4 g_FB1[64 * 32];         // 1 kc x 64 nf
__device__ uint4 g_FB2[16 * 64 * 32];
__device__ uint4 g_FB3[16 * 96 * 32];

__device__ __forceinline__ void mma_s8(int* c, const u32* a, u32 b0, u32 b1) {
    asm volatile(
        "mma.sync.aligned.m16n8k32.row.col.s32.s8.s8.s32 "
        "{%0,%1,%2,%3},{%4,%5,%6,%7},{%8,%9},{%0,%1,%2,%3};"
        : "+r"(c[0]), "+r"(c[1]), "+r"(c[2]), "+r"(c[3])
        : "r"(a[0]), "r"(a[1]), "r"(a[2]), "r"(a[3]), "r"(b0), "r"(b1));
}

__device__ __forceinline__ void quant2(float v, float inv, int& q1, int& q2) {
    float q = v * inv;                       // |q| <= 16256
    float f1 = rintf(q * 0.0078125f);
    q1 = (int)f1;
    q2 = (int)rintf(q - 128.f * f1);
}

__device__ __forceinline__ int abyte(int r, int k) {
    int kc = k >> 5, ko = k & 31;
    return (kc * 32 + (r & 7) * 4 + ((ko >> 2) & 3)) * 16
         + (((ko >> 4) << 1) + (r >> 3)) * 4 + (ko & 3);
}
__device__ __forceinline__ void qstore2(char* sm, int r, int k, float v0, float v1, float inv) {
    int a1, a2, c1, c2;
    quant2(v0, inv, a1, a2); quant2(v1, inv, c1, c2);
    int ad = abyte(r, k);
    *(short*)(sm + SM_AF1 + ad) = (short)((a1 & 0xff) | (c1 << 8));
    *(short*)(sm + SM_AF2 + ad) = (short)((a2 & 0xff) | (c2 << 8));
}
__device__ __forceinline__ void qstore1(char* sm, int r, int k, float v, float inv) {
    int a1, a2; quant2(v, inv, a1, a2);
    int ad = abyte(r, k);
    sm[SM_AF1 + ad] = (char)a1;
    sm[SM_AF2 + ad] = (char)a2;
}

// ---------------------------------------------------------------------------
template<int NT, int NCH, int NFN>
__device__ __forceinline__ void layer_s8_relu(
    char* sm, int tid, const uint4* __restrict__ Fq, int boff, u32* rm, int ri, int ro)
{
    const int wid = tid >> 5, lane = tid & 31;
    const int nf0 = wid * NT;
    const uint4* A1q = (const uint4*)(sm + SM_AF1);
    const uint4* A2q = (const uint4*)(sm + SM_AF2);
    const float* bias_sm = (const float*)(sm + SM_BIAS) + boff;
    const float* sb_sm   = (const float*)(sm + SM_SB)   + boff;

    int accH[NT][4], accM[NT][4];
#pragma unroll
    for (int nt = 0; nt < NT; ++nt)
#pragma unroll
        for (int q = 0; q < 4; ++q) { accH[nt][q] = 0; accM[nt][q] = 0; }

#pragma unroll
    for (int c = 0; c < NCH; ++c) {
        uint4 a1v = A1q[c * 32 + lane];
        uint4 a2v = A2q[c * 32 + lane];
        u32 A1[4] = {a1v.x, a1v.y, a1v.z, a1v.w};
        u32 A2[4] = {a2v.x, a2v.y, a2v.z, a2v.w};
#pragma unroll
        for (int g2 = 0; g2 < NT / 4; ++g2) {
            uint4 bf[4];
#pragma unroll
            for (int i = 0; i < 4; ++i)
                bf[i] = Fq[(c * NFN + nf0 + g2 * 4 + i) * 32 + lane];
#pragma unroll
            for (int i = 0; i < 4; ++i) {
                int nt = g2 * 4 + i;
                mma_s8(accH[nt], A1, bf[i].x, bf[i].y);
                mma_s8(accM[nt], A1, bf[i].z, bf[i].w);
                mma_s8(accM[nt], A2, bf[i].x, bf[i].y);
            }
        }
    }

    const int g = lane >> 2, t2 = (lane & 3) * 2;
    float sa0 = __uint_as_float(rm[ri + g])     * (1.f / 16256.f);
    float sa1 = __uint_as_float(rm[ri + g + 8]) * (1.f / 16256.f);
    float v[NT][4];
    float m0 = 0.f, m1 = 0.f;
#pragma unroll
    for (int nt = 0; nt < NT; ++nt) {
        int col = nf0 * 8 + nt * 8 + t2;
        float s0 = sb_sm[col], s1 = sb_sm[col + 1];
        float bb0 = bias_sm[col], bb1 = bias_sm[col + 1];
        v[nt][0] = fmaxf(fmaf(16384.f, (float)accH[nt][0], 128.f * (float)accM[nt][0]) * (sa0 * s0) + bb0, 0.f);
        v[nt][1] = fmaxf(fmaf(16384.f, (float)accH[nt][1], 128.f * (float)accM[nt][1]) * (sa0 * s1) + bb1, 0.f);
        v[nt][2] = fmaxf(fmaf(16384.f, (float)accH[nt][2], 128.f * (float)accM[nt][2]) * (sa1 * s0) + bb0, 0.f);
        v[nt][3] = fmaxf(fmaf(16384.f, (float)accH[nt][3], 128.f * (float)accM[nt][3]) * (sa1 * s1) + bb1, 0.f);
        m0 = fmaxf(m0, fmaxf(v[nt][0], v[nt][1]));
        m1 = fmaxf(m1, fmaxf(v[nt][2], v[nt][3]));
    }
    atomicMax(rm + ro + g,     __float_as_uint(m0));
    atomicMax(rm + ro + g + 8, __float_as_uint(m1));
    __syncthreads();   // rowmax done; all AF reads done

    float inv0 = 16256.f / __uint_as_float(rm[ro + g]);
    float inv1 = 16256.f / __uint_as_float(rm[ro + g + 8]);
#pragma unroll
    for (int nt = 0; nt < NT; ++nt) {
        int col = nf0 * 8 + nt * 8 + t2;
        qstore2(sm, g,     col, v[nt][0], v[nt][1], inv0);
        qstore2(sm, g + 8, col, v[nt][2], v[nt][3], inv1);
    }
    __syncthreads();   // AF ready for next layer
}

// ---------------------------------------------------------------------------
__device__ __forceinline__ void layer3_s8(char* sm, int tid, const u32* rm)
{
    const int wid = tid >> 5, lane = tid & 31;
    const uint4* A1q = (const uint4*)(sm + SM_AF1);
    const uint4* A2q = (const uint4*)(sm + SM_AF2);
    const uint4* Fq  = (const uint4*)g_FB3;
    const float* bias_sm = (const float*)(sm + SM_BIAS) + 1024;
    const float* sb_sm   = (const float*)(sm + SM_SB)   + 1024;
    const int g = lane >> 2, t2 = (lane & 3) * 2;
    float sa0 = __uint_as_float(rm[g])     * (1.f / 16256.f);
    float sa1 = __uint_as_float(rm[g + 8]) * (1.f / 16256.f);

#pragma unroll
    for (int h = 0; h < 2; ++h) {
        const int nf0 = h * 48 + wid * 6;
        int accH[6][4], accM[6][4];
#pragma unroll
        for (int nt = 0; nt < 6; ++nt)
#pragma unroll
            for (int q = 0; q < 4; ++q) { accH[nt][q] = 0; accM[nt][q] = 0; }

#pragma unroll
        for (int c = 0; c < 16; ++c) {
            uint4 a1v = A1q[c * 32 + lane];
            uint4 a2v = A2q[c * 32 + lane];
            u32 A1[4] = {a1v.x, a1v.y, a1v.z, a1v.w};
            u32 A2[4] = {a2v.x, a2v.y, a2v.z, a2v.w};
#pragma unroll
            for (int g2 = 0; g2 < 2; ++g2) {
                uint4 bf[3];
#pragma unroll
                for (int i = 0; i < 3; ++i)
                    bf[i] = Fq[(c * 96 + nf0 + g2 * 3 + i) * 32 + lane];
#pragma unroll
                for (int i = 0; i < 3; ++i) {
                    int nt = g2 * 3 + i;
                    mma_s8(accH[nt], A1, bf[i].x, bf[i].y);
                    mma_s8(accM[nt], A1, bf[i].z, bf[i].w);
                    mma_s8(accM[nt], A2, bf[i].x, bf[i].y);
                }
            }
        }
#pragma unroll
        for (int nt = 0; nt < 6; ++nt) {
            int scol = (nf0 + nt) * 8 + t2;
            float s0 = sb_sm[scol], s1 = sb_sm[scol + 1];
            float bb0 = bias_sm[scol], bb1 = bias_sm[scol + 1];
            float v0 = fmaf(16384.f, (float)accH[nt][0], 128.f * (float)accM[nt][0]) * (sa0 * s0) + bb0;
            float v1 = fmaf(16384.f, (float)accH[nt][1], 128.f * (float)accM[nt][1]) * (sa0 * s1) + bb1;
            float v2 = fmaf(16384.f, (float)accH[nt][2], 128.f * (float)accM[nt][2]) * (sa1 * s0) + bb0;
            float v3 = fmaf(16384.f, (float)accH[nt][3], 128.f * (float)accM[nt][3]) * (sa1 * s1) + bb1;
            *(float2*)(sm + SM_STASH + ((u32)g * ST_S + scol) * 4)       = make_float2(v0, v1);
            *(float2*)(sm + SM_STASH + ((u32)(g + 8) * ST_S + scol) * 4) = make_float2(v2, v3);
        }
    }
}

// ---------------------------------------------------------------------------
__device__ __forceinline__ float softplusf(float z) {
    return (z > 20.f) ? z : __logf(1.f + __expf(z));
}
__device__ __forceinline__ void spline_eval(const float raw[23], float xv,
                                            float &y_out, float &ld_out)
{
    float w[8], h[8];
    float mw = raw[0], mh = raw[8];
#pragma unroll
    for (int i = 1; i < 8; ++i) { mw = fmaxf(mw, raw[i]); mh = fmaxf(mh, raw[8 + i]); }
    float sw = 0.f, sh = 0.f;
#pragma unroll
    for (int i = 0; i < 8; ++i) {
        w[i] = __expf(raw[i] - mw); sw += w[i];
        h[i] = __expf(raw[8 + i] - mh); sh += h[i];
    }
    float iw = 6.f / sw, ih = 6.f / sh;
#pragma unroll
    for (int i = 0; i < 8; ++i) { w[i] *= iw; h[i] *= ih; }
    float der[9]; der[0] = 1.f; der[8] = 1.f;
#pragma unroll
    for (int i = 0; i < 7; ++i) der[i + 1] = softplusf(raw[16 + i]);
    float cw[9], ch[9]; cw[0] = -TAILB; ch[0] = -TAILB;
#pragma unroll
    for (int i = 0; i < 8; ++i) { cw[i + 1] = cw[i] + w[i]; ch[i + 1] = ch[i] + h[i]; }
    bool inside = (xv >= -TAILB) && (xv <= TAILB);
    float xc = fminf(fmaxf(xv, -TAILB + 1e-6f), TAILB - 1e-6f);
    int idx = 0;
#pragma unroll
    for (int i = 1; i <= 8; ++i) idx += (cw[i] < xc) ? 1 : 0;
    idx = min(idx, 7);
    float wk = w[0], hk = h[0], dk = der[0], dk1 = der[1], cwk = cw[0], chk = ch[0];
#pragma unroll
    for (int i = 1; i < 8; ++i) {
        bool sel = (idx == i);
        wk = sel ? w[i] : wk;   hk = sel ? h[i] : hk;
        dk = sel ? der[i] : dk; dk1 = sel ? der[i + 1] : dk1;
        cwk = sel ? cw[i] : cwk; chk = sel ? ch[i] : chk;
    }
    float xi = fminf(fmaxf((xc - cwk) / wk, 1e-6f), 1.f - 1e-6f);
    float om = 1.f - xi;
    float s = hk / wk;
    float num = hk * (s * xi * xi + dk * xi * om);
    float den = s + (dk + dk1 - 2.f * s) * xi * om;
    float yin = chk + num / den;
    float nld = s * s * (dk1 * xi * xi + 2.f * s * xi * om + dk * om * om);
    float ldin = __logf(nld + 1e-8f) - __logf(den * den + 1e-8f);
    y_out = inside ? yin : xv;
    ld_out = inside ? ldin : 0.f;
}

// ---------------------------------------------------------------------------
__global__ void __launch_bounds__(THREADS, 2)
spline_fused(const float* __restrict__ x,
             const float* __restrict__ b1, const float* __restrict__ b2,
             const float* __restrict__ b3, float* __restrict__ out)
{
    extern __shared__ char sm[];
    const int tid = threadIdx.x;
    const int wid = tid >> 5, lane = tid & 31;
    const int row0 = blockIdx.x * TM;
    u32* rm = (u32*)(sm + SM_RM);            // [0:16) x, [16:32) h1, [32:48) h2

    if (tid < 48) rm[tid] = __float_as_uint(1e-30f);
    {
        float* bias_sm = (float*)(sm + SM_BIAS);
        float* sb_sm   = (float*)(sm + SM_SB);
        for (int i = tid; i < 1792; i += THREADS) {
            float v;
            if (i < 512)       v = b1[i];
            else if (i < 1024) v = b2[i - 512];
            else { int j = i - 1024; v = (j < 736) ? b3[j] : 0.f; }
            bias_sm[i] = v;
            sb_sm[i] = g_sbg[i] * (1.f / 16256.f);
        }
    }
    // x pass 1: passthrough + XT + row |max|
#pragma unroll
    for (int it = 0; it < 4; ++it) {
        int idx = tid + it * THREADS;
        int r = idx >> 6, c = idx & 63;
        float v = x[(size_t)(row0 + r) * DIM + c];
        if (c < D_IN) {
            out[(size_t)(row0 + r) * DIM + c] = v;
            atomicMax(rm + r, __float_as_uint(fabsf(v)));
        } else {
            *(float*)(sm + SM_XT + (u32)(r * XT_S + (c - D_IN)) * 4) = v;
        }
    }
    __syncthreads();
    // x pass 2: quantize masked half
#pragma unroll
    for (int it = 0; it < 2; ++it) {
        int idx = tid + it * THREADS;
        int r = idx >> 5, c = idx & 31;
        float v = x[(size_t)(row0 + r) * DIM + c];
        float inv = 16256.f / __uint_as_float(rm[r]);
        qstore1(sm, r, c, v, inv);
    }
    __syncthreads();

    layer_s8_relu<8, 1, 64>(sm, tid, g_FB1, 0,    rm, 0, 16);
    layer_s8_relu<8, 16, 64>(sm, tid, g_FB2, 512, rm, 16, 32);
    layer3_s8(sm, tid, rm + 32);
    __syncthreads();

    // spline: warp w -> rows {w, w+8}
    const float* stashf = (const float*)(sm + SM_STASH);
    const float* xtf    = (const float*)(sm + SM_XT);
#pragma unroll
    for (int it = 0; it < 2; ++it) {
        int row = wid + it * 8, d = lane;
        float raw[23];
        const float* rp = stashf + (u32)row * ST_S + d * 23;
#pragma unroll
        for (int j = 0; j < 23; ++j) raw[j] = rp[j];
        float xv = xtf[row * XT_S + d];
        float yv, ld;
        spline_eval(raw, xv, yv, ld);
        int gr = row0 + row;
        out[(size_t)gr * DIM + D_IN + d] = yv;
#pragma unroll
        for (int off = 16; off; off >>= 1)
            ld += __shfl_xor_sync(0xffffffffu, ld, off);
        if (d == 0) out[(size_t)B_ROWS * DIM + gr] = ld;
    }
}

// ---------------------------------------------------------------------------
__global__ void __launch_bounds__(256)
prep_scale(const float* __restrict__ W1, const float* __restrict__ W2,
           const float* __restrict__ W3)
{
    int n = blockIdx.x * 256 + threadIdx.x;
    if (n >= 1792) return;
    float m = 0.f;
    if (n < 512) {
        for (int k = 0; k < 32; ++k) m = fmaxf(m, fabsf(W1[k * 512 + n]));
    } else if (n < 1024) {
        int nn = n - 512;
        for (int k = 0; k < 512; ++k) m = fmaxf(m, fabsf(W2[k * 512 + nn]));
    } else {
        int nn = n - 1024;
        if (nn < 736)
            for (int k = 0; k < 512; ++k) m = fmaxf(m, fabsf(W3[k * 736 + nn]));
    }
    g_sbg[n] = m;
}

__device__ __forceinline__ void packB(const float* __restrict__ W, int N, int nvalid,
                                      int k0, int n, float inv, u32& o1, u32& o2)
{
    u32 r1 = 0, r2 = 0;
#pragma unroll
    for (int i = 0; i < 4; ++i) {
        float v = (n < nvalid) ? W[(size_t)(k0 + i) * N + n] : 0.f;
        int q1, q2; quant2(v, inv, q1, q2);
        r1 |= (u32)(q1 & 0xff) << (8 * i);
        r2 |= (u32)(q2 & 0xff) << (8 * i);
    }
    o1 = r1; o2 = r2;
}

__global__ void __launch_bounds__(256)
prep_pack(const float* __restrict__ W1, const float* __restrict__ W2,
          const float* __restrict__ W3)
{
    const int T1 = 2048, T2 = 32768, T3 = 49152;
    for (int id = blockIdx.x * 256 + threadIdx.x; id < T1 + T2 + T3;
         id += gridDim.x * 256) {
        const float* W; int N, nvalid, sboff, kc, nf, lane; uint4* F; int base;
        if (id < T1) {
            lane = id & 31; int fid = id >> 5;
            nf = fid; kc = 0; W = W1; N = 512; nvalid = 512; sboff = 0;
            F = g_FB1; base = fid * 32 + lane;
        } else if (id < T1 + T2) {
            int i = id - T1; lane = i & 31; int fid = i >> 5;
            nf = fid % 64; kc = fid / 64; W = W2; N = 512; nvalid = 512; sboff = 512;
            F = g_FB2; base = fid * 32 + lane;
        } else {
            int i = id - T1 - T2; lane = i & 31; int fid = i >> 5;
            nf = fid % 96; kc = fid / 96; W = W3; N = 736; nvalid = 736; sboff = 1024;
            F = g_FB3; base = fid * 32 + lane;
        }
        int n = nf * 8 + (lane >> 2);
        float cm = g_sbg[sboff + n];
        float inv = (cm > 0.f) ? 16256.f / cm : 0.f;
        int k0 = kc * 32 + (lane & 3) * 4;
        u32 b1a, b2a, b1b, b2b;
        packB(W, N, nvalid, k0,      n, inv, b1a, b2a);
        packB(W, N, nvalid, k0 + 16, n, inv, b1b, b2b);
        F[base] = make_uint4(b1a, b1b, b2a, b2b);
    }
}

// ---------------------------------------------------------------------------
extern "C" void kernel_launch(void* const* d_in, const int* in_sizes, int n_in,
                              void* d_out, int out_size)
{
    (void)in_sizes; (void)n_in; (void)out_size;
    const float* x  = (const float*)d_in[0];
    const float* W1 = (const float*)d_in[1];
    const float* b1 = (const float*)d_in[2];
    const float* W2 = (const float*)d_in[3];
    const float* b2 = (const float*)d_in[4];
    const float* W3 = (const float*)d_in[5];
    const float* b3 = (const float*)d_in[6];
    float* out = (float*)d_out;

    prep_scale<<<7, 256>>>(W1, W2, W3);
    prep_pack<<<328, 256>>>(W1, W2, W3);

    cudaFuncSetAttribute(spline_fused,
                         cudaFuncAttributeMaxDynamicSharedMemorySize, SM_TOTAL);
    spline_fused<<<B_ROWS / TM, THREADS, SM_TOTAL>>>(x, b1, b2, b3, out);
}

// round 14
// speedup vs baseline: 3.1704x; 3.1704x over previous
#include <cuda_runtime.h>
#include <cuda_fp16.h>
#include <cstdint>

// ===========================================================================
// SplineCouplingLayer — fused HMMA fp16-split (round 14)
//  hi pass (ah*bh) in fp32-accum mma; lo passes (al*bh + ah*bl) in fp16-accum
//  mma (2x rate hypothesis). fp16 2-digit split = 22-bit operands.
// ===========================================================================

#define B_ROWS  131072
#define DIM     64
#define D_IN    32
#define TAILB   3.0f
#define TM      16
#define THREADS 256

#define XT_S   33
#define XA_S   40
#define H_S    520
#define ST_S   776

#define SM_XT    0            // 16*33*4  = 2112
#define SM_BIAS  2112         // 1792*4   = 7168
#define SM_XAH   9280         // 16*40*2  = 1280
#define SM_XAL   10560
#define SM_H1H   11840        // 16*520*2 = 16640
#define SM_H1L   28480
#define SM_H2H   45120
#define SM_H2L   61760        // ends 78400
#define SM_STASH 9280         // 16*776*4 = 49664 (overlays XA/H1 after sync)
#define SM_TOTAL 78400

typedef unsigned int u32;

// W fragments: per (kc, nf): 32 lanes x uint4 {b0h, b1h, b0l, b1l} (fp16)
__device__ u32 g_F1[2 * 64 * 32 * 4];
__device__ u32 g_F2[32 * 64 * 32 * 4];
__device__ u32 g_F3[32 * 96 * 32 * 4];

__device__ __forceinline__ u32 smem_u32(const void* p) {
    u32 a;
    asm("{ .reg .u64 t; cvta.to.shared.u64 t, %1; cvt.u32.u64 %0, t; }"
        : "=r"(a) : "l"(p));
    return a;
}

#define LDSM_X4(r0, r1, r2, r3, a) \
    asm volatile("ldmatrix.sync.aligned.m8n8.x4.shared.b16 {%0,%1,%2,%3}, [%4];" \
                 : "=r"(r0), "=r"(r1), "=r"(r2), "=r"(r3) : "r"(a))

// fp16 inputs, fp32 accum
__device__ __forceinline__ void mma_f32(float* c, const u32* a, u32 b0, u32 b1) {
    asm volatile(
        "mma.sync.aligned.m16n8k16.row.col.f32.f16.f16.f32 "
        "{%0,%1,%2,%3},{%4,%5,%6,%7},{%8,%9},{%0,%1,%2,%3};"
        : "+f"(c[0]), "+f"(c[1]), "+f"(c[2]), "+f"(c[3])
        : "r"(a[0]), "r"(a[1]), "r"(a[2]), "r"(a[3]), "r"(b0), "r"(b1));
}
// fp16 inputs, fp16 accum (2 x f16x2 regs)
__device__ __forceinline__ void mma_f16(u32* c, const u32* a, u32 b0, u32 b1) {
    asm volatile(
        "mma.sync.aligned.m16n8k16.row.col.f16.f16.f16.f16 "
        "{%0,%1},{%2,%3,%4,%5},{%6,%7},{%0,%1};"
        : "+r"(c[0]), "+r"(c[1])
        : "r"(a[0]), "r"(a[1]), "r"(a[2]), "r"(a[3]), "r"(b0), "r"(b1));
}

__device__ __forceinline__ u32 pk2h(__half a, __half b) {
    return (u32)__half_as_ushort(a) | ((u32)__half_as_ushort(b) << 16);
}
__device__ __forceinline__ void split2h(float x, float y, u32 &hi, u32 &lo) {
    __half xh = __float2half_rn(x);
    __half yh = __float2half_rn(y);
    __half xl = __float2half_rn(x - __half2float(xh));
    __half yl = __float2half_rn(y - __half2float(yh));
    hi = pk2h(xh, yh);
    lo = pk2h(xl, yl);
}
__device__ __forceinline__ float lo_half(u32 v, int which) {
    __half h = __ushort_as_half((unsigned short)(which ? (v >> 16) : (v & 0xffff)));
    return __half2float(h);
}

__device__ __forceinline__ void load_afrag(
    u32 smb, int aoff_h, int aoff_l, int AS, int lane, int cK,
    u32 ah[4], u32 al[4])
{
    int r  = (lane & 7) + ((lane >> 3) & 1) * 8;
    int cc = cK + (lane >> 4) * 8;
    u32 off = (u32)(r * AS + cc) * 2;
    LDSM_X4(ah[0], ah[1], ah[2], ah[3], smb + aoff_h + off);
    LDSM_X4(al[0], al[1], al[2], al[3], smb + aoff_l + off);
}

// ---------------------------------------------------------------------------
// Layers 1/2: NT=8 n-tiles per warp (8 warps cover N=512)
// ---------------------------------------------------------------------------
template<int NT, int NCH, int NFN, bool RELU>
__device__ __forceinline__ void do_layer_lin(
    char* sm, u32 smb, int tid, const u32* __restrict__ F, int bias_off,
    int aoff_h, int aoff_l, int AS, int hoff_h, int hoff_l)
{
    const int wid = tid >> 5, lane = tid & 31;
    const int nf0 = wid * NT;
    const uint4* Fq = (const uint4*)F;
    const float* bias_sm = (const float*)(sm + SM_BIAS) + bias_off;

    float accF[NT][4];
    u32   accL[NT][2];
#pragma unroll
    for (int nt = 0; nt < NT; ++nt) {
#pragma unroll
        for (int q = 0; q < 4; ++q) accF[nt][q] = 0.f;
        accL[nt][0] = 0u; accL[nt][1] = 0u;
    }

#pragma unroll
    for (int c = 0; c < NCH; ++c) {
        u32 ah[4], al[4];
        load_afrag(smb, aoff_h, aoff_l, AS, lane, c * 16, ah, al);
#pragma unroll
        for (int g2 = 0; g2 < NT / 4; ++g2) {
            uint4 b[4];
#pragma unroll
            for (int i = 0; i < 4; ++i)
                b[i] = Fq[(c * NFN + nf0 + g2 * 4 + i) * 32 + lane];
#pragma unroll
            for (int i = 0; i < 4; ++i) {
                int nt = g2 * 4 + i;
                mma_f32(accF[nt], ah, b[i].x, b[i].y);
                mma_f16(accL[nt], al, b[i].x, b[i].y);
                mma_f16(accL[nt], ah, b[i].z, b[i].w);
            }
        }
    }

    const int g  = lane >> 2;
    const int t2 = (lane & 3) * 2;
#pragma unroll
    for (int nt = 0; nt < NT; ++nt) {
        int col = nf0 * 8 + nt * 8 + t2;
        float b0v = bias_sm[col], b1v = bias_sm[col + 1];
        float v0 = accF[nt][0] + lo_half(accL[nt][0], 0) + b0v;
        float v1 = accF[nt][1] + lo_half(accL[nt][0], 1) + b1v;
        float v2 = accF[nt][2] + lo_half(accL[nt][1], 0) + b0v;
        float v3 = accF[nt][3] + lo_half(accL[nt][1], 1) + b1v;
        if (RELU) {
            v0 = fmaxf(v0, 0.f); v1 = fmaxf(v1, 0.f);
            v2 = fmaxf(v2, 0.f); v3 = fmaxf(v3, 0.f);
        }
        u32 h01, l01, h23, l23;
        split2h(v0, v1, h01, l01);
        split2h(v2, v3, h23, l23);
        u32 oA = (u32)(g * H_S + col) * 2;
        u32 oB = (u32)((g + 8) * H_S + col) * 2;
        *(u32*)(sm + hoff_h + oA) = h01;
        *(u32*)(sm + hoff_l + oA) = l01;
        *(u32*)(sm + hoff_h + oB) = h23;
        *(u32*)(sm + hoff_l + oB) = l23;
    }
}

// ---------------------------------------------------------------------------
// Layer 3: two halves of NT=6 -> fp32 stash (after caller sync)
// ---------------------------------------------------------------------------
__device__ __forceinline__ void do_layer3_main(
    char* sm, u32 smb, int tid, const u32* __restrict__ F,
    int aoff_h, int aoff_l, int AS, float accF[2][6][4], u32 accL[2][6][2])
{
    const int wid = tid >> 5, lane = tid & 31;
    const uint4* Fq = (const uint4*)F;

#pragma unroll
    for (int hh = 0; hh < 2; ++hh)
#pragma unroll
        for (int nt = 0; nt < 6; ++nt) {
#pragma unroll
            for (int q = 0; q < 4; ++q) accF[hh][nt][q] = 0.f;
            accL[hh][nt][0] = 0u; accL[hh][nt][1] = 0u;
        }

#pragma unroll
    for (int c = 0; c < 32; ++c) {
        u32 ah[4], al[4];
        load_afrag(smb, aoff_h, aoff_l, AS, lane, c * 16, ah, al);
#pragma unroll
        for (int hh = 0; hh < 2; ++hh) {
            const int nf0 = hh * 48 + wid * 6;
#pragma unroll
            for (int g2 = 0; g2 < 2; ++g2) {
                uint4 b[3];
#pragma unroll
                for (int i = 0; i < 3; ++i)
                    b[i] = Fq[(c * 96 + nf0 + g2 * 3 + i) * 32 + lane];
#pragma unroll
                for (int i = 0; i < 3; ++i) {
                    int nt = g2 * 3 + i;
                    mma_f32(accF[hh][nt], ah, b[i].x, b[i].y);
                    mma_f16(accL[hh][nt], al, b[i].x, b[i].y);
                    mma_f16(accL[hh][nt], ah, b[i].z, b[i].w);
                }
            }
        }
    }
}

__device__ __forceinline__ void do_layer3_epi(
    char* sm, int tid, float accF[2][6][4], u32 accL[2][6][2])
{
    const int wid = tid >> 5, lane = tid & 31;
    const float* bias_sm = (const float*)(sm + SM_BIAS) + 1024;
    const int g  = lane >> 2;
    const int t2 = (lane & 3) * 2;
#pragma unroll
    for (int hh = 0; hh < 2; ++hh)
#pragma unroll
        for (int nt = 0; nt < 6; ++nt) {
            int scol = hh * 384 + wid * 48 + nt * 8 + t2;
            float b0v = bias_sm[scol], b1v = bias_sm[scol + 1];
            float v0 = accF[hh][nt][0] + lo_half(accL[hh][nt][0], 0) + b0v;
            float v1 = accF[hh][nt][1] + lo_half(accL[hh][nt][0], 1) + b1v;
            float v2 = accF[hh][nt][2] + lo_half(accL[hh][nt][1], 0) + b0v;
            float v3 = accF[hh][nt][3] + lo_half(accL[hh][nt][1], 1) + b1v;
            *(float2*)(sm + SM_STASH + ((u32)g * ST_S + scol) * 4)
                = make_float2(v0, v1);
            *(float2*)(sm + SM_STASH + ((u32)(g + 8) * ST_S + scol) * 4)
                = make_float2(v2, v3);
        }
}

// ---------------------------------------------------------------------------
__device__ __forceinline__ float softplusf(float z) {
    return (z > 20.f) ? z : __logf(1.f + __expf(z));
}
__device__ __forceinline__ void spline_eval(const float raw[23], float xv,
                                            float &y_out, float &ld_out)
{
    float w[8], h[8];
    float mw = raw[0], mh = raw[8];
#pragma unroll
    for (int i = 1; i < 8; ++i) { mw = fmaxf(mw, raw[i]); mh = fmaxf(mh, raw[8 + i]); }
    float sw = 0.f, sh = 0.f;
#pragma unroll
    for (int i = 0; i < 8; ++i) {
        w[i] = __expf(raw[i] - mw); sw += w[i];
        h[i] = __expf(raw[8 + i] - mh); sh += h[i];
    }
    float iw = 6.f / sw, ih = 6.f / sh;
#pragma unroll
    for (int i = 0; i < 8; ++i) { w[i] *= iw; h[i] *= ih; }
    float der[9]; der[0] = 1.f; der[8] = 1.f;
#pragma unroll
    for (int i = 0; i < 7; ++i) der[i + 1] = softplusf(raw[16 + i]);
    float cw[9], ch[9]; cw[0] = -TAILB; ch[0] = -TAILB;
#pragma unroll
    for (int i = 0; i < 8; ++i) { cw[i + 1] = cw[i] + w[i]; ch[i + 1] = ch[i] + h[i]; }
    bool inside = (xv >= -TAILB) && (xv <= TAILB);
    float xc = fminf(fmaxf(xv, -TAILB + 1e-6f), TAILB - 1e-6f);
    int idx = 0;
#pragma unroll
    for (int i = 1; i <= 8; ++i) idx += (cw[i] < xc) ? 1 : 0;
    idx = min(idx, 7);
    float wk = w[0], hk = h[0], dk = der[0], dk1 = der[1], cwk = cw[0], chk = ch[0];
#pragma unroll
    for (int i = 1; i < 8; ++i) {
        bool sel = (idx == i);
        wk = sel ? w[i] : wk;   hk = sel ? h[i] : hk;
        dk = sel ? der[i] : dk; dk1 = sel ? der[i + 1] : dk1;
        cwk = sel ? cw[i] : cwk; chk = sel ? ch[i] : chk;
    }
    float xi = fminf(fmaxf((xc - cwk) / wk, 1e-6f), 1.f - 1e-6f);
    float om = 1.f - xi;
    float s = hk / wk;
    float num = hk * (s * xi * xi + dk * xi * om);
    float den = s + (dk + dk1 - 2.f * s) * xi * om;
    float yin = chk + num / den;
    float nld = s * s * (dk1 * xi * xi + 2.f * s * xi * om + dk * om * om);
    float ldin = __logf(nld + 1e-8f) - __logf(den * den + 1e-8f);
    y_out = inside ? yin : xv;
    ld_out = inside ? ldin : 0.f;
}

// ---------------------------------------------------------------------------
__global__ void __launch_bounds__(THREADS, 2)
spline_fused(const float* __restrict__ x,
             const float* __restrict__ b1, const float* __restrict__ b2,
             const float* __restrict__ b3, float* __restrict__ out)
{
    extern __shared__ char sm[];
    const u32 smb = smem_u32(sm);
    const int tid  = threadIdx.x;
    const int wid  = tid >> 5, lane = tid & 31;
    const int row0 = blockIdx.x * TM;

    {
        float* bias_sm = (float*)(sm + SM_BIAS);
        for (int i = tid; i < 1792; i += THREADS) {
            float v;
            if (i < 512)       v = b1[i];
            else if (i < 1024) v = b2[i - 512];
            else { int j = i - 1024; v = (j < 736) ? b3[j] : 0.f; }
            bias_sm[i] = v;
        }
    }
#pragma unroll
    for (int it = 0; it < 4; ++it) {
        int idx = tid + it * THREADS;
        int r = idx >> 6, c = idx & 63;
        float v = x[(size_t)(row0 + r) * DIM + c];
        if (c < D_IN) {
            out[(size_t)(row0 + r) * DIM + c] = v;
            __half hh = __float2half_rn(v);
            __half ll = __float2half_rn(v - __half2float(hh));
            *(__half*)(sm + SM_XAH + (u32)(r * XA_S + c) * 2) = hh;
            *(__half*)(sm + SM_XAL + (u32)(r * XA_S + c) * 2) = ll;
        } else {
            *(float*)(sm + SM_XT + (u32)(r * XT_S + (c - D_IN)) * 4) = v;
        }
    }
    __syncthreads();

    do_layer_lin<8, 2, 64, true>(sm, smb, tid, g_F1, 0,
                                 SM_XAH, SM_XAL, XA_S, SM_H1H, SM_H1L);
    __syncthreads();
    do_layer_lin<8, 32, 64, true>(sm, smb, tid, g_F2, 512,
                                  SM_H1H, SM_H1L, H_S, SM_H2H, SM_H2L);
    __syncthreads();

    float accF3[2][6][4];
    u32   accL3[2][6][2];
    do_layer3_main(sm, smb, tid, g_F3, SM_H2H, SM_H2L, H_S, accF3, accL3);
    __syncthreads();
    do_layer3_epi(sm, tid, accF3, accL3);
    __syncthreads();

    // spline: warp w -> rows {w, w+8}
    const float* stashf = (const float*)(sm + SM_STASH);
    const float* xtf    = (const float*)(sm + SM_XT);
#pragma unroll
    for (int it = 0; it < 2; ++it) {
        int row = wid + it * 8, d = lane;
        float raw[23];
        const float* rp = stashf + (u32)row * ST_S + d * 23;
#pragma unroll
        for (int j = 0; j < 23; ++j) raw[j] = rp[j];
        float xv = xtf[row * XT_S + d];
        float yv, ld;
        spline_eval(raw, xv, yv, ld);
        int gr = row0 + row;
        out[(size_t)gr * DIM + D_IN + d] = yv;
#pragma unroll
        for (int off = 16; off; off >>= 1)
            ld += __shfl_xor_sync(0xffffffffu, ld, off);
        if (d == 0) out[(size_t)B_ROWS * DIM + gr] = ld;
    }
}

// ---------------------------------------------------------------------------
// prep: pack W into fp16 hi/lo fragment-order uint4 {b0h, b1h, b0l, b1l}
// ---------------------------------------------------------------------------
__device__ __forceinline__ void frag_pack(
    const float* __restrict__ W, int N, int nvalid, int k0, int n, int t,
    u32* __restrict__ F, u32 base)
{
    float w00 = 0.f, w01 = 0.f, w10 = 0.f, w11 = 0.f;
    if (n < nvalid) {
        w00 = W[(size_t)(k0 + 2 * t)     * N + n];
        w01 = W[(size_t)(k0 + 2 * t + 1) * N + n];
        w10 = W[(size_t)(k0 + 2 * t + 8) * N + n];
        w11 = W[(size_t)(k0 + 2 * t + 9) * N + n];
    }
    u32 b0h, b0l, b1h, b1l;
    split2h(w00, w01, b0h, b0l);
    split2h(w10, w11, b1h, b1l);
    ((uint4*)F)[base] = make_uint4(b0h, b1h, b0l, b1l);
}

__global__ void __launch_bounds__(256)
prep_kernel(const float* __restrict__ W1, const float* __restrict__ W2,
            const float* __restrict__ W3)
{
    const int T1 = 2 * 64 * 32;
    const int T2 = 32 * 64 * 32;
    const int T3 = 32 * 96 * 32;
    for (int id = blockIdx.x * 256 + threadIdx.x; id < T1 + T2 + T3;
         id += gridDim.x * 256) {
        if (id < T1) {
            int lane = id & 31, fid = id >> 5;
            int nf = fid % 64, kc = fid / 64;
            frag_pack(W1, 512, 512, kc * 16, nf * 8 + (lane >> 2), lane & 3,
                      g_F1, (u32)(fid * 32 + lane));
        } else if (id < T1 + T2) {
            int i = id - T1;
            int lane = i & 31, fid = i >> 5;
            int nf = fid % 64, kc = fid / 64;
            frag_pack(W2, 512, 512, kc * 16, nf * 8 + (lane >> 2), lane & 3,
                      g_F2, (u32)(fid * 32 + lane));
        } else {
            int i = id - T1 - T2;
            int lane = i & 31, fid = i >> 5;
            int nf = fid % 96, kc = fid / 96;
            frag_pack(W3, 736, 736, kc * 16, nf * 8 + (lane >> 2), lane & 3,
                      g_F3, (u32)(fid * 32 + lane));
        }
    }
}

// ---------------------------------------------------------------------------
extern "C" void kernel_launch(void* const* d_in, const int* in_sizes, int n_in,
                              void* d_out, int out_size)
{
    (void)in_sizes; (void)n_in; (void)out_size;
    const float* x  = (const float*)d_in[0];
    const float* W1 = (const float*)d_in[1];
    const float* b1 = (const float*)d_in[2];
    const float* W2 = (const float*)d_in[3];
    const float* b2 = (const float*)d_in[4];
    const float* W3 = (const float*)d_in[5];
    const float* b3 = (const float*)d_in[6];
    float* out = (float*)d_out;

    prep_kernel<<<656, 256>>>(W1, W2, W3);

    cudaFuncSetAttribute(spline_fused,
                         cudaFuncAttributeMaxDynamicSharedMemorySize, SM_TOTAL);
    spline_fused<<<B_ROWS / TM, THREADS, SM_TOTAL>>>(x, b1, b2, b3, out);
}

// round 15
// speedup vs baseline: 4.5580x; 1.4377x over previous
#include <cuda_runtime.h>
#include <cuda_fp16.h>
#include <cstdint>

// ===========================================================================
// SplineCouplingLayer — fused HMMA 2-pass asymmetric split (round 15)
//  activations: fp16 hi+lo (22 bits); weights: plain fp16 (11 bits)
//  pass1 ah*b (fp32 accum), pass2 al*b (fp16 accum)  -> 2/3 mma count
// ===========================================================================

#define B_ROWS  131072
#define DIM     64
#define D_IN    32
#define TAILB   3.0f
#define TM      16
#define THREADS 256

#define XT_S   33
#define XA_S   40
#define H_S    520
#define ST_S   776

#define SM_XT    0            // 16*33*4  = 2112
#define SM_BIAS  2112         // 1792*4   = 7168
#define SM_XAH   9280         // 16*40*2  = 1280
#define SM_XAL   10560
#define SM_H1H   11840        // 16*520*2 = 16640
#define SM_H1L   28480
#define SM_H2H   45120
#define SM_H2L   61760        // ends 78400
#define SM_STASH 9280         // 16*776*4 = 49664 (overlays XA/H1 after sync)
#define SM_TOTAL 78400

typedef unsigned int u32;

// W fragments (fp16): per (kc, nf): 32 lanes x uint2 {b0, b1}
__device__ uint2 g_F1[2 * 64 * 32];
__device__ uint2 g_F2[32 * 64 * 32];
__device__ uint2 g_F3[32 * 96 * 32];

__device__ __forceinline__ u32 smem_u32(const void* p) {
    u32 a;
    asm("{ .reg .u64 t; cvta.to.shared.u64 t, %1; cvt.u32.u64 %0, t; }"
        : "=r"(a) : "l"(p));
    return a;
}

#define LDSM_X4(r0, r1, r2, r3, a) \
    asm volatile("ldmatrix.sync.aligned.m8n8.x4.shared.b16 {%0,%1,%2,%3}, [%4];" \
                 : "=r"(r0), "=r"(r1), "=r"(r2), "=r"(r3) : "r"(a))

// fp16 in, fp32 accum
__device__ __forceinline__ void mma_f32(float* c, const u32* a, u32 b0, u32 b1) {
    asm volatile(
        "mma.sync.aligned.m16n8k16.row.col.f32.f16.f16.f32 "
        "{%0,%1,%2,%3},{%4,%5,%6,%7},{%8,%9},{%0,%1,%2,%3};"
        : "+f"(c[0]), "+f"(c[1]), "+f"(c[2]), "+f"(c[3])
        : "r"(a[0]), "r"(a[1]), "r"(a[2]), "r"(a[3]), "r"(b0), "r"(b1));
}
// fp16 in, fp16 accum
__device__ __forceinline__ void mma_f16(u32* c, const u32* a, u32 b0, u32 b1) {
    asm volatile(
        "mma.sync.aligned.m16n8k16.row.col.f16.f16.f16.f16 "
        "{%0,%1},{%2,%3,%4,%5},{%6,%7},{%0,%1};"
        : "+r"(c[0]), "+r"(c[1])
        : "r"(a[0]), "r"(a[1]), "r"(a[2]), "r"(a[3]), "r"(b0), "r"(b1));
}

__device__ __forceinline__ u32 pk2h(__half a, __half b) {
    return (u32)__half_as_ushort(a) | ((u32)__half_as_ushort(b) << 16);
}
__device__ __forceinline__ void split2h(float x, float y, u32 &hi, u32 &lo) {
    __half xh = __float2half_rn(x);
    __half yh = __float2half_rn(y);
    __half xl = __float2half_rn(x - __half2float(xh));
    __half yl = __float2half_rn(y - __half2float(yh));
    hi = pk2h(xh, yh);
    lo = pk2h(xl, yl);
}
__device__ __forceinline__ float lo_half(u32 v, int which) {
    __half h = __ushort_as_half((unsigned short)(which ? (v >> 16) : (v & 0xffff)));
    return __half2float(h);
}

__device__ __forceinline__ void load_afrag(
    u32 smb, int aoff_h, int aoff_l, int AS, int lane, int cK,
    u32 ah[4], u32 al[4])
{
    int r  = (lane & 7) + ((lane >> 3) & 1) * 8;
    int cc = cK + (lane >> 4) * 8;
    u32 off = (u32)(r * AS + cc) * 2;
    LDSM_X4(ah[0], ah[1], ah[2], ah[3], smb + aoff_h + off);
    LDSM_X4(al[0], al[1], al[2], al[3], smb + aoff_l + off);
}

// ---------------------------------------------------------------------------
// Layers 1/2: NT=8 n-tiles per warp (8 warps cover N=512)
// ---------------------------------------------------------------------------
template<int NT, int NCH, int NFN, bool RELU>
__device__ __forceinline__ void do_layer_lin(
    char* sm, u32 smb, int tid, const uint2* __restrict__ Fq, int bias_off,
    int aoff_h, int aoff_l, int AS, int hoff_h, int hoff_l)
{
    const int wid = tid >> 5, lane = tid & 31;
    const int nf0 = wid * NT;
    const float* bias_sm = (const float*)(sm + SM_BIAS) + bias_off;

    float accF[NT][4];
    u32   accL[NT][2];
#pragma unroll
    for (int nt = 0; nt < NT; ++nt) {
#pragma unroll
        for (int q = 0; q < 4; ++q) accF[nt][q] = 0.f;
        accL[nt][0] = 0u; accL[nt][1] = 0u;
    }

#pragma unroll
    for (int c = 0; c < NCH; ++c) {
        u32 ah[4], al[4];
        load_afrag(smb, aoff_h, aoff_l, AS, lane, c * 16, ah, al);
#pragma unroll
        for (int g2 = 0; g2 < NT / 4; ++g2) {
            uint2 b[4];
#pragma unroll
            for (int i = 0; i < 4; ++i)
                b[i] = Fq[(c * NFN + nf0 + g2 * 4 + i) * 32 + lane];
#pragma unroll
            for (int i = 0; i < 4; ++i) {
                int nt = g2 * 4 + i;
                mma_f32(accF[nt], ah, b[i].x, b[i].y);
                mma_f16(accL[nt], al, b[i].x, b[i].y);
            }
        }
    }

    const int g  = lane >> 2;
    const int t2 = (lane & 3) * 2;
#pragma unroll
    for (int nt = 0; nt < NT; ++nt) {
        int col = nf0 * 8 + nt * 8 + t2;
        float b0v = bias_sm[col], b1v = bias_sm[col + 1];
        float v0 = accF[nt][0] + lo_half(accL[nt][0], 0) + b0v;
        float v1 = accF[nt][1] + lo_half(accL[nt][0], 1) + b1v;
        float v2 = accF[nt][2] + lo_half(accL[nt][1], 0) + b0v;
        float v3 = accF[nt][3] + lo_half(accL[nt][1], 1) + b1v;
        if (RELU) {
            v0 = fmaxf(v0, 0.f); v1 = fmaxf(v1, 0.f);
            v2 = fmaxf(v2, 0.f); v3 = fmaxf(v3, 0.f);
        }
        u32 h01, l01, h23, l23;
        split2h(v0, v1, h01, l01);
        split2h(v2, v3, h23, l23);
        u32 oA = (u32)(g * H_S + col) * 2;
        u32 oB = (u32)((g + 8) * H_S + col) * 2;
        *(u32*)(sm + hoff_h + oA) = h01;
        *(u32*)(sm + hoff_l + oA) = l01;
        *(u32*)(sm + hoff_h + oB) = h23;
        *(u32*)(sm + hoff_l + oB) = l23;
    }
}

// ---------------------------------------------------------------------------
// Layer 3: two halves of NT=6 -> fp32 stash (after caller sync)
// ---------------------------------------------------------------------------
__device__ __forceinline__ void do_layer3_main(
    char* sm, u32 smb, int tid, const uint2* __restrict__ Fq,
    int aoff_h, int aoff_l, int AS, float accF[2][6][4], u32 accL[2][6][2])
{
    const int wid = tid >> 5, lane = tid & 31;

#pragma unroll
    for (int hh = 0; hh < 2; ++hh)
#pragma unroll
        for (int nt = 0; nt < 6; ++nt) {
#pragma unroll
            for (int q = 0; q < 4; ++q) accF[hh][nt][q] = 0.f;
            accL[hh][nt][0] = 0u; accL[hh][nt][1] = 0u;
        }

#pragma unroll
    for (int c = 0; c < 32; ++c) {
        u32 ah[4], al[4];
        load_afrag(smb, aoff_h, aoff_l, AS, lane, c * 16, ah, al);
#pragma unroll
        for (int hh = 0; hh < 2; ++hh) {
            const int nf0 = hh * 48 + wid * 6;
#pragma unroll
            for (int g2 = 0; g2 < 2; ++g2) {
                uint2 b[3];
#pragma unroll
                for (int i = 0; i < 3; ++i)
                    b[i] = Fq[(c * 96 + nf0 + g2 * 3 + i) * 32 + lane];
#pragma unroll
                for (int i = 0; i < 3; ++i) {
                    int nt = g2 * 3 + i;
                    mma_f32(accF[hh][nt], ah, b[i].x, b[i].y);
                    mma_f16(accL[hh][nt], al, b[i].x, b[i].y);
                }
            }
        }
    }
}

__device__ __forceinline__ void do_layer3_epi(
    char* sm, int tid, float accF[2][6][4], u32 accL[2][6][2])
{
    const int wid = tid >> 5, lane = tid & 31;
    const float* bias_sm = (const float*)(sm + SM_BIAS) + 1024;
    const int g  = lane >> 2;
    const int t2 = (lane & 3) * 2;
#pragma unroll
    for (int hh = 0; hh < 2; ++hh)
#pragma unroll
        for (int nt = 0; nt < 6; ++nt) {
            int scol = hh * 384 + wid * 48 + nt * 8 + t2;
            float b0v = bias_sm[scol], b1v = bias_sm[scol + 1];
            float v0 = accF[hh][nt][0] + lo_half(accL[hh][nt][0], 0) + b0v;
            float v1 = accF[hh][nt][1] + lo_half(accL[hh][nt][0], 1) + b1v;
            float v2 = accF[hh][nt][2] + lo_half(accL[hh][nt][1], 0) + b0v;
            float v3 = accF[hh][nt][3] + lo_half(accL[hh][nt][1], 1) + b1v;
            *(float2*)(sm + SM_STASH + ((u32)g * ST_S + scol) * 4)
                = make_float2(v0, v1);
            *(float2*)(sm + SM_STASH + ((u32)(g + 8) * ST_S + scol) * 4)
                = make_float2(v2, v3);
        }
}

// ---------------------------------------------------------------------------
__device__ __forceinline__ float softplusf(float z) {
    return (z > 20.f) ? z : __logf(1.f + __expf(z));
}
__device__ __forceinline__ void spline_eval(const float raw[23], float xv,
                                            float &y_out, float &ld_out)
{
    float w[8], h[8];
    float mw = raw[0], mh = raw[8];
#pragma unroll
    for (int i = 1; i < 8; ++i) { mw = fmaxf(mw, raw[i]); mh = fmaxf(mh, raw[8 + i]); }
    float sw = 0.f, sh = 0.f;
#pragma unroll
    for (int i = 0; i < 8; ++i) {
        w[i] = __expf(raw[i] - mw); sw += w[i];
        h[i] = __expf(raw[8 + i] - mh); sh += h[i];
    }
    float iw = 6.f / sw, ih = 6.f / sh;
#pragma unroll
    for (int i = 0; i < 8; ++i) { w[i] *= iw; h[i] *= ih; }
    float der[9]; der[0] = 1.f; der[8] = 1.f;
#pragma unroll
    for (int i = 0; i < 7; ++i) der[i + 1] = softplusf(raw[16 + i]);
    float cw[9], ch[9]; cw[0] = -TAILB; ch[0] = -TAILB;
#pragma unroll
    for (int i = 0; i < 8; ++i) { cw[i + 1] = cw[i] + w[i]; ch[i + 1] = ch[i] + h[i]; }
    bool inside = (xv >= -TAILB) && (xv <= TAILB);
    float xc = fminf(fmaxf(xv, -TAILB + 1e-6f), TAILB - 1e-6f);
    int idx = 0;
#pragma unroll
    for (int i = 1; i <= 8; ++i) idx += (cw[i] < xc) ? 1 : 0;
    idx = min(idx, 7);
    float wk = w[0], hk = h[0], dk = der[0], dk1 = der[1], cwk = cw[0], chk = ch[0];
#pragma unroll
    for (int i = 1; i < 8; ++i) {
        bool sel = (idx == i);
        wk = sel ? w[i] : wk;   hk = sel ? h[i] : hk;
        dk = sel ? der[i] : dk; dk1 = sel ? der[i + 1] : dk1;
        cwk = sel ? cw[i] : cwk; chk = sel ? ch[i] : chk;
    }
    float xi = fminf(fmaxf((xc - cwk) / wk, 1e-6f), 1.f - 1e-6f);
    float om = 1.f - xi;
    float s = hk / wk;
    float num = hk * (s * xi * xi + dk * xi * om);
    float den = s + (dk + dk1 - 2.f * s) * xi * om;
    float yin = chk + num / den;
    float nld = s * s * (dk1 * xi * xi + 2.f * s * xi * om + dk * om * om);
    float ldin = __logf(nld + 1e-8f) - __logf(den * den + 1e-8f);
    y_out = inside ? yin : xv;
    ld_out = inside ? ldin : 0.f;
}

// ---------------------------------------------------------------------------
__global__ void __launch_bounds__(THREADS, 2)
spline_fused(const float* __restrict__ x,
             const float* __restrict__ b1, const float* __restrict__ b2,
             const float* __restrict__ b3, float* __restrict__ out)
{
    extern __shared__ char sm[];
    const u32 smb = smem_u32(sm);
    const int tid  = threadIdx.x;
    const int wid  = tid >> 5, lane = tid & 31;
    const int row0 = blockIdx.x * TM;

    {
        float* bias_sm = (float*)(sm + SM_BIAS);
        for (int i = tid; i < 1792; i += THREADS) {
            float v;
            if (i < 512)       v = b1[i];
            else if (i < 1024) v = b2[i - 512];
            else { int j = i - 1024; v = (j < 736) ? b3[j] : 0.f; }
            bias_sm[i] = v;
        }
    }
#pragma unroll
    for (int it = 0; it < 4; ++it) {
        int idx = tid + it * THREADS;
        int r = idx >> 6, c = idx & 63;
        float v = x[(size_t)(row0 + r) * DIM + c];
        if (c < D_IN) {
            out[(size_t)(row0 + r) * DIM + c] = v;
            __half hh = __float2half_rn(v);
            __half ll = __float2half_rn(v - __half2float(hh));
            *(__half*)(sm + SM_XAH + (u32)(r * XA_S + c) * 2) = hh;
            *(__half*)(sm + SM_XAL + (u32)(r * XA_S + c) * 2) = ll;
        } else {
            *(float*)(sm + SM_XT + (u32)(r * XT_S + (c - D_IN)) * 4) = v;
        }
    }
    __syncthreads();

    do_layer_lin<8, 2, 64, true>(sm, smb, tid, g_F1, 0,
                                 SM_XAH, SM_XAL, XA_S, SM_H1H, SM_H1L);
    __syncthreads();
    do_layer_lin<8, 32, 64, true>(sm, smb, tid, g_F2, 512,
                                  SM_H1H, SM_H1L, H_S, SM_H2H, SM_H2L);
    __syncthreads();

    float accF3[2][6][4];
    u32   accL3[2][6][2];
    do_layer3_main(sm, smb, tid, g_F3, SM_H2H, SM_H2L, H_S, accF3, accL3);
    __syncthreads();
    do_layer3_epi(sm, tid, accF3, accL3);
    __syncthreads();

    // spline: warp w -> rows {w, w+8}
    const float* stashf = (const float*)(sm + SM_STASH);
    const float* xtf    = (const float*)(sm + SM_XT);
#pragma unroll
    for (int it = 0; it < 2; ++it) {
        int row = wid + it * 8, d = lane;
        float raw[23];
        const float* rp = stashf + (u32)row * ST_S + d * 23;
#pragma unroll
        for (int j = 0; j < 23; ++j) raw[j] = rp[j];
        float xv = xtf[row * XT_S + d];
        float yv, ld;
        spline_eval(raw, xv, yv, ld);
        int gr = row0 + row;
        out[(size_t)gr * DIM + D_IN + d] = yv;
#pragma unroll
        for (int off = 16; off; off >>= 1)
            ld += __shfl_xor_sync(0xffffffffu, ld, off);
        if (d == 0) out[(size_t)B_ROWS * DIM + gr] = ld;
    }
}

// ---------------------------------------------------------------------------
// prep: pack W (rounded to fp16) into fragment-order uint2 {b0, b1}
// ---------------------------------------------------------------------------
__device__ __forceinline__ void frag_pack(
    const float* __restrict__ W, int N, int nvalid, int k0, int n, int t,
    uint2* __restrict__ F, u32 base)
{
    float w00 = 0.f, w01 = 0.f, w10 = 0.f, w11 = 0.f;
    if (n < nvalid) {
        w00 = W[(size_t)(k0 + 2 * t)     * N + n];
        w01 = W[(size_t)(k0 + 2 * t + 1) * N + n];
        w10 = W[(size_t)(k0 + 2 * t + 8) * N + n];
        w11 = W[(size_t)(k0 + 2 * t + 9) * N + n];
    }
    u32 b0 = pk2h(__float2half_rn(w00), __float2half_rn(w01));
    u32 b1 = pk2h(__float2half_rn(w10), __float2half_rn(w11));
    F[base] = make_uint2(b0, b1);
}

__global__ void __launch_bounds__(256)
prep_kernel(const float* __restrict__ W1, const float* __restrict__ W2,
            const float* __restrict__ W3)
{
    const int T1 = 2 * 64 * 32;
    const int T2 = 32 * 64 * 32;
    const int T3 = 32 * 96 * 32;
    for (int id = blockIdx.x * 256 + threadIdx.x; id < T1 + T2 + T3;
         id += gridDim.x * 256) {
        if (id < T1) {
            int lane = id & 31, fid = id >> 5;
            int nf = fid % 64, kc = fid / 64;
            frag_pack(W1, 512, 512, kc * 16, nf * 8 + (lane >> 2), lane & 3,
                      g_F1, (u32)(fid * 32 + lane));
        } else if (id < T1 + T2) {
            int i = id - T1;
            int lane = i & 31, fid = i >> 5;
            int nf = fid % 64, kc = fid / 64;
            frag_pack(W2, 512, 512, kc * 16, nf * 8 + (lane >> 2), lane & 3,
                      g_F2, (u32)(fid * 32 + lane));
        } else {
            int i = id - T1 - T2;
            int lane = i & 31, fid = i >> 5;
            int nf = fid % 96, kc = fid / 96;
            frag_pack(W3, 736, 736, kc * 16, nf * 8 + (lane >> 2), lane & 3,
                      g_F3, (u32)(fid * 32 + lane));
        }
    }
}

// ---------------------------------------------------------------------------
extern "C" void kernel_launch(void* const* d_in, const int* in_sizes, int n_in,
                              void* d_out, int out_size)
{
    (void)in_sizes; (void)n_in; (void)out_size;
    const float* x  = (const float*)d_in[0];
    const float* W1 = (const float*)d_in[1];
    const float* b1 = (const float*)d_in[2];
    const float* W2 = (const float*)d_in[3];
    const float* b2 = (const float*)d_in[4];
    const float* W3 = (const float*)d_in[5];
    const float* b3 = (const float*)d_in[6];
    float* out = (float*)d_out;

    prep_kernel<<<656, 256>>>(W1, W2, W3);

    cudaFuncSetAttribute(spline_fused,
                         cudaFuncAttributeMaxDynamicSharedMemorySize, SM_TOTAL);
    spline_fused<<<B_ROWS / TM, THREADS, SM_TOTAL>>>(x, b1, b2, b3, out);
}